// round 14
// baseline (speedup 1.0000x reference)
#include <cuda_runtime.h>
#include <math.h>

#define N_TOK 768
#define D_MODEL 512
#define CZ 128
#define NH 16
#define DH 32
#define LN_EPS 1e-5f
#define PSW 772
#define BIAS_ITILES 8

// ---------------- scratch ----------------
__device__ float g_q[N_TOK * D_MODEL];
__device__ float g_k[N_TOK * D_MODEL];
__device__ float g_v[N_TOK * D_MODEL];
__device__ float g_g[N_TOK * D_MODEL];
__device__ float g_o[N_TOK * D_MODEL];
__device__ float g_logits[(size_t)NH * N_TOK * N_TOK];  // bias (read by attn)
__device__ float g_A[NH * CZ];
__device__ float g_SA[NH];
__device__ float g_CB[NH];

__device__ __forceinline__ unsigned f2tf32(float x) {
    unsigned r;
    asm("cvt.rna.tf32.f32 %0, %1;" : "=r"(r) : "f"(x));
    return r;
}
__device__ __forceinline__ unsigned bits(float x) { return __float_as_uint(x); }

__device__ __forceinline__ void split2(float x, float& hi, float& lo) {
    hi = __uint_as_float(f2tf32(x));
    lo = x - hi;
}

__device__ __forceinline__ void mma_tf32(float* d,
                                         unsigned a0, unsigned a1, unsigned a2, unsigned a3,
                                         unsigned b0, unsigned b1) {
    asm volatile(
        "mma.sync.aligned.m16n8k8.row.col.f32.tf32.tf32.f32 "
        "{%0,%1,%2,%3}, {%4,%5,%6,%7}, {%8,%9}, {%0,%1,%2,%3};"
        : "+f"(d[0]), "+f"(d[1]), "+f"(d[2]), "+f"(d[3])
        : "r"(a0), "r"(a1), "r"(a2), "r"(a3), "r"(b0), "r"(b1));
}

__device__ __forceinline__ void mma3(float* d, const unsigned* ah, const unsigned* al,
                                     unsigned bh0, unsigned bh1, unsigned bl0, unsigned bl1) {
    mma_tf32(d, ah[0], ah[1], ah[2], ah[3], bh0, bh1);
    mma_tf32(d, ah[0], ah[1], ah[2], ah[3], bl0, bl1);
    mma_tf32(d, al[0], al[1], al[2], al[3], bh0, bh1);
}

__device__ __forceinline__ void cp_async16(unsigned dst, const void* src) {
    asm volatile("cp.async.cg.shared.global [%0], [%1], 16;" :: "r"(dst), "l"(src));
}

// ---------------- K0: fold LN affine into Wz ----------------
__global__ void prep_kernel(const float* __restrict__ Wz,
                            const float* __restrict__ lnw,
                            const float* __restrict__ lnb) {
    __shared__ float red[8];
    int c = threadIdx.x;
    float wc = lnw[c], bc = lnb[c];
    for (int h = 0; h < NH; h++) {
        float wz = Wz[h * CZ + c];
        float a = wz * wc;
        g_A[h * CZ + c] = a;
        float sa = a, cb = wz * bc;
        for (int o = 16; o; o >>= 1) {
            sa += __shfl_down_sync(0xffffffffu, sa, o);
            cb += __shfl_down_sync(0xffffffffu, cb, o);
        }
        if ((c & 31) == 0) { red[c >> 5] = sa; red[4 + (c >> 5)] = cb; }
        __syncthreads();
        if (c == 0) {
            g_SA[h] = red[0] + red[1] + red[2] + red[3];
            g_CB[h] = red[4] + red[5] + red[6] + red[7];
        }
        __syncthreads();
    }
}

// ---------------- K1: projections, dual-plane 3xTF32, BM=BN=64 (r10 proven) ----------------
__global__ void proj_kernel(const float* __restrict__ s,
                            const float* __restrict__ Wq, const float* __restrict__ bq,
                            const float* __restrict__ Wk, const float* __restrict__ Wv,
                            const float* __restrict__ Wg) {
    __shared__ float sh[64][20], sl[64][20], wh[64][20], wl[64][20];
    int w = blockIdx.z;
    const float* W = (w == 0) ? Wq : (w == 1) ? Wk : (w == 2) ? Wv : Wg;
    float* C = (w == 0) ? g_q : (w == 1) ? g_k : (w == 2) ? g_v : g_g;
    int bm = blockIdx.y * 64, bn = blockIdx.x * 64;
    int tid = threadIdx.x;
    int wid = tid >> 5, lane = tid & 31;
    int mtile = wid & 3, ntile = wid >> 2;
    int gr = lane >> 2, tig = lane & 3;
    int lr = tid >> 2, lc = (tid & 3) * 4;
    float acc[4][4] = {};

    for (int k0 = 0; k0 < D_MODEL; k0 += 16) {
        {
            float4 v = *reinterpret_cast<const float4*>(&s[(bm + lr) * D_MODEL + k0 + lc]);
            split2(v.x, sh[lr][lc], sl[lr][lc]);
            split2(v.y, sh[lr][lc + 1], sl[lr][lc + 1]);
            split2(v.z, sh[lr][lc + 2], sl[lr][lc + 2]);
            split2(v.w, sh[lr][lc + 3], sl[lr][lc + 3]);
            float4 u = *reinterpret_cast<const float4*>(&W[(bn + lr) * D_MODEL + k0 + lc]);
            split2(u.x, wh[lr][lc], wl[lr][lc]);
            split2(u.y, wh[lr][lc + 1], wl[lr][lc + 1]);
            split2(u.z, wh[lr][lc + 2], wl[lr][lc + 2]);
            split2(u.w, wh[lr][lc + 3], wl[lr][lc + 3]);
        }
        __syncthreads();
#pragma unroll
        for (int kk = 0; kk < 16; kk += 8) {
            int mr = mtile * 16 + gr;
            unsigned ah[4], al[4];
            ah[0] = bits(sh[mr][kk + tig]);     al[0] = bits(sl[mr][kk + tig]);
            ah[1] = bits(sh[mr + 8][kk + tig]); al[1] = bits(sl[mr + 8][kk + tig]);
            ah[2] = bits(sh[mr][kk + tig + 4]);     al[2] = bits(sl[mr][kk + tig + 4]);
            ah[3] = bits(sh[mr + 8][kk + tig + 4]); al[3] = bits(sl[mr + 8][kk + tig + 4]);
#pragma unroll
            for (int ni = 0; ni < 4; ni++) {
                int nr = ntile * 32 + ni * 8 + gr;
                unsigned bh0 = bits(wh[nr][kk + tig]), bl0 = bits(wl[nr][kk + tig]);
                unsigned bh1 = bits(wh[nr][kk + tig + 4]), bl1 = bits(wl[nr][kk + tig + 4]);
                mma3(acc[ni], ah, al, bh0, bh1, bl0, bl1);
            }
        }
        __syncthreads();
    }
#pragma unroll
    for (int ni = 0; ni < 4; ni++) {
        int m = bm + mtile * 16 + gr;
        int n = bn + ntile * 32 + ni * 8 + 2 * tig;
        float b0 = 0.f, b1 = 0.f;
        if (w == 0) { b0 = bq[n]; b1 = bq[n + 1]; }
        *reinterpret_cast<float2*>(&C[m * D_MODEL + n]) =
            make_float2(acc[ni][0] + b0, acc[ni][1] + b1);
        *reinterpret_cast<float2*>(&C[(m + 8) * D_MODEL + n]) =
            make_float2(acc[ni][2] + b0, acc[ni][3] + b1);
    }
}

// ---------------- K2: pair bias, cp.async pipeline + hoisted conversions ----------------
__global__ void bias_kernel(const float* __restrict__ z) {
    extern __shared__ float bsm[];
    float* zbuf[2] = {bsm, bsm + 64 * 132};
    float* As = bsm + 2 * 64 * 132;
    float* mu_s = As + 16 * 132;
    float* rs_s = mu_s + 64;
    int j0 = blockIdx.x * 64;
    int ibase = blockIdx.y * BIAS_ITILES;
    int tid = threadIdx.x;

    for (int e = tid; e < 16 * 32; e += 256) {
        int h = e >> 5, c4 = (e & 31) * 4;
        float4 v = *reinterpret_cast<const float4*>(&g_A[h * CZ + c4]);
        *reinterpret_cast<float4*>(&As[h * 132 + c4]) = v;
    }
    {
        const float* zb = z + ((size_t)ibase * N_TOK + j0) * CZ;
        unsigned dst = (unsigned)__cvta_generic_to_shared(zbuf[0]);
#pragma unroll
        for (int it = 0; it < 8; it++) {
            int f4 = tid + it * 256;
            int r = f4 >> 5, c4 = f4 & 31;
            cp_async16(dst + (r * 132 + c4 * 4) * 4, zb + r * CZ + c4 * 4);
        }
        asm volatile("cp.async.commit_group;");
    }

    int w = tid >> 5, lane = tid & 31;
    int mtile = w & 3, ntile = w >> 2;
    int gr = lane >> 2, tig = lane & 3;
    int srow = tid >> 2, ssub = tid & 3;

    __syncthreads();  // As visible to all threads

    // Hoist A-matrix (B-side) fragment conversions: tile-invariant across all 8 i-tiles
    unsigned hb0[16], hb1[16];
    {
        const float* ar = &As[(ntile * 8 + gr) * 132];
#pragma unroll
        for (int k = 0; k < 16; k++) {
            hb0[k] = f2tf32(ar[k * 8 + tig]);
            hb1[k] = f2tf32(ar[k * 8 + tig + 4]);
        }
    }

    for (int t = 0; t < BIAS_ITILES; t++) {
        float* cur = zbuf[t & 1];
        if (t + 1 < BIAS_ITILES) {
            const float* zb = z + ((size_t)(ibase + t + 1) * N_TOK + j0) * CZ;
            unsigned dst = (unsigned)__cvta_generic_to_shared(zbuf[(t + 1) & 1]);
#pragma unroll
            for (int it = 0; it < 8; it++) {
                int f4 = tid + it * 256;
                int r = f4 >> 5, c4 = f4 & 31;
                cp_async16(dst + (r * 132 + c4 * 4) * 4, zb + r * CZ + c4 * 4);
            }
            asm volatile("cp.async.commit_group;");
            asm volatile("cp.async.wait_group 1;");
        } else {
            asm volatile("cp.async.wait_group 0;");
        }
        __syncthreads();

        // stats pass + in-place tf32 conversion (each element touched by exactly one thread)
        {
            float sm = 0.f, sq = 0.f;
#pragma unroll
            for (int c4 = 0; c4 < 8; c4++) {
                float4* p = reinterpret_cast<float4*>(&cur[srow * 132 + (ssub * 8 + c4) * 4]);
                float4 v = *p;
                sm += v.x + v.y + v.z + v.w;
                sq += v.x * v.x + v.y * v.y + v.z * v.z + v.w * v.w;
                v.x = __uint_as_float(f2tf32(v.x));
                v.y = __uint_as_float(f2tf32(v.y));
                v.z = __uint_as_float(f2tf32(v.z));
                v.w = __uint_as_float(f2tf32(v.w));
                *p = v;
            }
            sm += __shfl_xor_sync(0xffffffffu, sm, 1);
            sm += __shfl_xor_sync(0xffffffffu, sm, 2);
            sq += __shfl_xor_sync(0xffffffffu, sq, 1);
            sq += __shfl_xor_sync(0xffffffffu, sq, 2);
            if (ssub == 0) {
                float m = sm * (1.0f / CZ);
                float var = sq * (1.0f / CZ) - m * m;
                mu_s[srow] = m;
                rs_s[srow] = rsqrtf(var + LN_EPS);
            }
        }
        __syncthreads();

        const float* zr0 = &cur[(mtile * 16 + gr) * 132];
        const float* zr1 = &cur[(mtile * 16 + gr + 8) * 132];

        float d[4] = {};
#pragma unroll
        for (int k = 0; k < 16; k++) {
            unsigned a0 = bits(zr0[k * 8 + tig]);
            unsigned a1 = bits(zr1[k * 8 + tig]);
            unsigned a2 = bits(zr0[k * 8 + tig + 4]);
            unsigned a3 = bits(zr1[k * 8 + tig + 4]);
            mma_tf32(d, a0, a1, a2, a3, hb0[k], hb1[k]);
        }

        int i = ibase + t;
        int jl = mtile * 16 + gr;
        int jh = jl + 8;
        int h0 = ntile * 8 + 2 * tig, h1 = h0 + 1;
        float mu_l = mu_s[jl], rs_l = rs_s[jl];
        float mu_h = mu_s[jh], rs_h = rs_s[jh];
        float sa0 = g_SA[h0], cb0 = g_CB[h0];
        float sa1 = g_SA[h1], cb1 = g_CB[h1];
        g_logits[((size_t)h0 * N_TOK + i) * N_TOK + j0 + jl] = rs_l * (d[0] - mu_l * sa0) + cb0;
        g_logits[((size_t)h1 * N_TOK + i) * N_TOK + j0 + jl] = rs_l * (d[1] - mu_l * sa1) + cb1;
        g_logits[((size_t)h0 * N_TOK + i) * N_TOK + j0 + jh] = rs_h * (d[2] - mu_h * sa0) + cb0;
        g_logits[((size_t)h1 * N_TOK + i) * N_TOK + j0 + jh] = rs_h * (d[3] - mu_h * sa1) + cb1;
        __syncthreads();
    }
}

// ---------------- K3: fused attention, 32 q-rows/block, 2 m-frags per warp (r13 proven) ----------------
__global__ __launch_bounds__(256, 2) void attn_kernel() {
    extern __shared__ float sm_[];
    float* Ps = sm_;                     // [32][PSW]; front 8192 reused for reduction
    float* inv_s = Ps + 32 * PSW;        // [32]
    int h = blockIdx.y;
    int i0 = blockIdx.x * 32;
    int tid = threadIdx.x;
    int wid = tid >> 5, lane = tid & 31;
    int gr = lane >> 2, tig = lane & 3;
    const float scale = 0.17677669529663687f;
    int jw = wid * 96;

    {
        unsigned qa_h[2][4][4], qa_l[2][4][4];
        const float* qb = g_q + (size_t)i0 * D_MODEL + h * DH;
#pragma unroll
        for (int mi = 0; mi < 2; mi++) {
#pragma unroll
            for (int kk4 = 0; kk4 < 4; kk4++) {
                int k = kk4 * 8;
                int r0 = mi * 16 + gr, r1 = mi * 16 + gr + 8;
                float hi, lo;
                split2(qb[r0 * D_MODEL + k + tig] * scale, hi, lo);
                qa_h[mi][kk4][0] = bits(hi); qa_l[mi][kk4][0] = bits(lo);
                split2(qb[r1 * D_MODEL + k + tig] * scale, hi, lo);
                qa_h[mi][kk4][1] = bits(hi); qa_l[mi][kk4][1] = bits(lo);
                split2(qb[r0 * D_MODEL + k + tig + 4] * scale, hi, lo);
                qa_h[mi][kk4][2] = bits(hi); qa_l[mi][kk4][2] = bits(lo);
                split2(qb[r1 * D_MODEL + k + tig + 4] * scale, hi, lo);
                qa_h[mi][kk4][3] = bits(hi); qa_l[mi][kk4][3] = bits(lo);
            }
        }

        const float* kb = g_k + h * DH;
        const float* bb = g_logits + ((size_t)h * N_TOK + i0) * N_TOK;
#pragma unroll
        for (int f = 0; f < 12; f++) {
            int n0 = jw + f * 8;
            float acc[2][4] = {};
#pragma unroll
            for (int kk4 = 0; kk4 < 4; kk4++) {
                int k = kk4 * 8;
                float hi, lo;
                unsigned bh0, bl0, bh1, bl1;
                split2(kb[(n0 + gr) * D_MODEL + k + tig], hi, lo); bh0 = bits(hi); bl0 = bits(lo);
                split2(kb[(n0 + gr) * D_MODEL + k + tig + 4], hi, lo); bh1 = bits(hi); bl1 = bits(lo);
#pragma unroll
                for (int mi = 0; mi < 2; mi++)
                    mma3(acc[mi], qa_h[mi][kk4], qa_l[mi][kk4], bh0, bh1, bl0, bl1);
            }
            int jc = n0 + 2 * tig;
#pragma unroll
            for (int mi = 0; mi < 2; mi++) {
                int r0 = mi * 16 + gr, r1 = mi * 16 + gr + 8;
                float2 b0 = *reinterpret_cast<const float2*>(&bb[r0 * N_TOK + jc]);
                float2 b1 = *reinterpret_cast<const float2*>(&bb[r1 * N_TOK + jc]);
                *reinterpret_cast<float2*>(&Ps[r0 * PSW + jc]) =
                    make_float2(acc[mi][0] + b0.x, acc[mi][1] + b0.y);
                *reinterpret_cast<float2*>(&Ps[r1 * PSW + jc]) =
                    make_float2(acc[mi][2] + b1.x, acc[mi][3] + b1.y);
            }
        }
    }
    __syncthreads();

#pragma unroll
    for (int rr = 0; rr < 4; rr++) {
        int r = wid * 4 + rr;
        float v[24];
        float mx = -1e30f;
#pragma unroll
        for (int t = 0; t < 24; t++) {
            v[t] = Ps[r * PSW + lane + 32 * t];
            mx = fmaxf(mx, v[t]);
        }
#pragma unroll
        for (int o = 16; o; o >>= 1) mx = fmaxf(mx, __shfl_xor_sync(0xffffffffu, mx, o));
        float sum = 0.f;
#pragma unroll
        for (int t = 0; t < 24; t++) { v[t] = __expf(v[t] - mx); sum += v[t]; }
#pragma unroll
        for (int o = 16; o; o >>= 1) sum += __shfl_xor_sync(0xffffffffu, sum, o);
        if (lane == 0) inv_s[r] = 1.0f / sum;
#pragma unroll
        for (int t = 0; t < 24; t++) Ps[r * PSW + lane + 32 * t] = v[t];
    }
    __syncthreads();

    float acc2[2][4][4] = {};
    {
        const float* vb = g_v + h * DH;
#pragma unroll
        for (int kk = 0; kk < 96; kk += 8) {
            int kg = jw + kk;
            unsigned ah[2][4], al[2][4];
            float hi, lo;
#pragma unroll
            for (int mi = 0; mi < 2; mi++) {
                int r0 = mi * 16 + gr, r1 = mi * 16 + gr + 8;
                split2(Ps[r0 * PSW + kg + tig], hi, lo);     ah[mi][0] = bits(hi); al[mi][0] = bits(lo);
                split2(Ps[r1 * PSW + kg + tig], hi, lo);     ah[mi][1] = bits(hi); al[mi][1] = bits(lo);
                split2(Ps[r0 * PSW + kg + tig + 4], hi, lo); ah[mi][2] = bits(hi); al[mi][2] = bits(lo);
                split2(Ps[r1 * PSW + kg + tig + 4], hi, lo); ah[mi][3] = bits(hi); al[mi][3] = bits(lo);
            }
#pragma unroll
            for (int ni = 0; ni < 4; ni++) {
                float b0f = vb[(kg + tig) * D_MODEL + ni * 8 + gr];
                float b1f = vb[(kg + tig + 4) * D_MODEL + ni * 8 + gr];
                unsigned bh0, bl0, bh1, bl1;
                split2(b0f, hi, lo); bh0 = bits(hi); bl0 = bits(lo);
                split2(b1f, hi, lo); bh1 = bits(hi); bl1 = bits(lo);
#pragma unroll
                for (int mi = 0; mi < 2; mi++)
                    mma3(acc2[mi][ni], ah[mi], al[mi], bh0, bh1, bl0, bl1);
            }
        }
    }
    __syncthreads();  // all Ps reads done; safe to reuse Ps front as reduction buffer

    float* red = Ps;
#pragma unroll
    for (int mi = 0; mi < 2; mi++) {
#pragma unroll
        for (int ni = 0; ni < 4; ni++) {
            int r0 = mi * 16 + gr, r1 = mi * 16 + gr + 8;
            *reinterpret_cast<float2*>(&red[wid * 1024 + r0 * 32 + ni * 8 + 2 * tig]) =
                make_float2(acc2[mi][ni][0], acc2[mi][ni][1]);
            *reinterpret_cast<float2*>(&red[wid * 1024 + r1 * 32 + ni * 8 + 2 * tig]) =
                make_float2(acc2[mi][ni][2], acc2[mi][ni][3]);
        }
    }
    __syncthreads();
    {
        int e0 = tid * 4;
        int i = e0 >> 5, d = e0 & 31;
        float4 sum = make_float4(0.f, 0.f, 0.f, 0.f);
#pragma unroll
        for (int w = 0; w < 8; w++) {
            float4 p = *reinterpret_cast<float4*>(&red[w * 1024 + e0]);
            sum.x += p.x; sum.y += p.y; sum.z += p.z; sum.w += p.w;
        }
        float iv = inv_s[i];
        *reinterpret_cast<float4*>(&g_o[(size_t)(i0 + i) * D_MODEL + h * DH + d]) =
            make_float4(sum.x * iv, sum.y * iv, sum.z * iv, sum.w * iv);
    }
}

// ---------------- K4: out = (o * sigmoid(g)) @ Wo^T, dual-plane, BM=BN=64 (r10 proven) ----------------
__global__ void out_kernel(const float* __restrict__ Wo, float* __restrict__ out) {
    __shared__ float sh[64][20], sl[64][20], wh[64][20], wl[64][20];
    int bm = blockIdx.y * 64, bn = blockIdx.x * 64;
    int tid = threadIdx.x;
    int wid = tid >> 5, lane = tid & 31;
    int mtile = wid & 3, ntile = wid >> 2;
    int gr = lane >> 2, tig = lane & 3;
    int lr = tid >> 2, lc = (tid & 3) * 4;
    float acc[4][4] = {};

    for (int k0 = 0; k0 < D_MODEL; k0 += 16) {
        {
            float4 va = *reinterpret_cast<const float4*>(&g_o[(bm + lr) * D_MODEL + k0 + lc]);
            float4 vg = *reinterpret_cast<const float4*>(&g_g[(bm + lr) * D_MODEL + k0 + lc]);
            va.x *= 1.0f / (1.0f + __expf(-vg.x));
            va.y *= 1.0f / (1.0f + __expf(-vg.y));
            va.z *= 1.0f / (1.0f + __expf(-vg.z));
            va.w *= 1.0f / (1.0f + __expf(-vg.w));
            split2(va.x, sh[lr][lc], sl[lr][lc]);
            split2(va.y, sh[lr][lc + 1], sl[lr][lc + 1]);
            split2(va.z, sh[lr][lc + 2], sl[lr][lc + 2]);
            split2(va.w, sh[lr][lc + 3], sl[lr][lc + 3]);
            float4 u = *reinterpret_cast<const float4*>(&Wo[(bn + lr) * D_MODEL + k0 + lc]);
            split2(u.x, wh[lr][lc], wl[lr][lc]);
            split2(u.y, wh[lr][lc + 1], wl[lr][lc + 1]);
            split2(u.z, wh[lr][lc + 2], wl[lr][lc + 2]);
            split2(u.w, wh[lr][lc + 3], wl[lr][lc + 3]);
        }
        __syncthreads();
#pragma unroll
        for (int kk = 0; kk < 16; kk += 8) {
            int mr = mtile * 16 + gr;
            unsigned ah[4], al[4];
            ah[0] = bits(sh[mr][kk + tig]);     al[0] = bits(sl[mr][kk + tig]);
            ah[1] = bits(sh[mr + 8][kk + tig]); al[1] = bits(sl[mr + 8][kk + tig]);
            ah[2] = bits(sh[mr][kk + tig + 4]);     al[2] = bits(sl[mr][kk + tig + 4]);
            ah[3] = bits(sh[mr + 8][kk + tig + 4]); al[3] = bits(sl[mr + 8][kk + tig + 4]);
#pragma unroll
            for (int ni = 0; ni < 4; ni++) {
                int nr = ntile * 32 + ni * 8 + gr;
                unsigned bh0 = bits(wh[nr][kk + tig]), bl0 = bits(wl[nr][kk + tig]);
                unsigned bh1 = bits(wh[nr][kk + tig + 4]), bl1 = bits(wl[nr][kk + tig + 4]);
                mma3(acc[ni], ah, al, bh0, bh1, bl0, bl1);
            }
        }
        __syncthreads();
    }
#pragma unroll
    for (int ni = 0; ni < 4; ni++) {
        int m = bm + mtile * 16 + gr;
        int n = bn + ntile * 32 + ni * 8 + 2 * tig;
        *reinterpret_cast<float2*>(&out[m * D_MODEL + n]) = make_float2(acc[ni][0], acc[ni][1]);
        *reinterpret_cast<float2*>(&out[(m + 8) * D_MODEL + n]) = make_float2(acc[ni][2], acc[ni][3]);
    }
}

// ---------------- launch ----------------
extern "C" void kernel_launch(void* const* d_in, const int* in_sizes, int n_in,
                              void* d_out, int out_size) {
    const float* s   = (const float*)d_in[0];
    const float* z   = (const float*)d_in[1];
    const float* Wq  = (const float*)d_in[2];
    const float* bq  = (const float*)d_in[3];
    const float* Wk  = (const float*)d_in[4];
    const float* Wv  = (const float*)d_in[5];
    const float* Wg  = (const float*)d_in[6];
    const float* Wo  = (const float*)d_in[7];
    const float* lnw = (const float*)d_in[8];
    const float* lnb = (const float*)d_in[9];
    const float* Wz  = (const float*)d_in[10];
    float* out = (float*)d_out;

    const int attn_smem = (32 * PSW + 32) * 4;
    cudaFuncSetAttribute(attn_kernel, cudaFuncAttributeMaxDynamicSharedMemorySize, attn_smem);
    const int bias_smem = (2 * 64 * 132 + 16 * 132 + 128) * 4;
    cudaFuncSetAttribute(bias_kernel, cudaFuncAttributeMaxDynamicSharedMemorySize, bias_smem);

    prep_kernel<<<1, 128>>>(Wz, lnw, lnb);
    proj_kernel<<<dim3(D_MODEL / 64, N_TOK / 64, 4), 256>>>(s, Wq, bq, Wk, Wv, Wg);
    bias_kernel<<<dim3(N_TOK / 64, N_TOK / BIAS_ITILES), 256, bias_smem>>>(z);
    attn_kernel<<<dim3(N_TOK / 32, NH), 256, attn_smem>>>();
    out_kernel<<<dim3(D_MODEL / 64, N_TOK / 64), 256>>>(Wo, out);
}

// round 15
// speedup vs baseline: 1.1235x; 1.1235x over previous
#include <cuda_runtime.h>
#include <math.h>

#define N_TOK 768
#define D_MODEL 512
#define CZ 128
#define NH 16
#define DH 32
#define LN_EPS 1e-5f
#define PSW 772
#define BIAS_ITILES 8

// ---------------- scratch ----------------
__device__ float g_q[N_TOK * D_MODEL];
__device__ float g_k[N_TOK * D_MODEL];
__device__ float g_v[N_TOK * D_MODEL];
__device__ float g_g[N_TOK * D_MODEL];
__device__ float g_o[N_TOK * D_MODEL];
__device__ float g_logits[(size_t)NH * N_TOK * N_TOK];  // bias (read by attn)
__device__ float g_A[NH * CZ];
__device__ float g_SA[NH];
__device__ float g_CB[NH];

__device__ __forceinline__ unsigned f2tf32(float x) {
    unsigned r;
    asm("cvt.rna.tf32.f32 %0, %1;" : "=r"(r) : "f"(x));
    return r;
}
__device__ __forceinline__ unsigned bits(float x) { return __float_as_uint(x); }

__device__ __forceinline__ void split2(float x, float& hi, float& lo) {
    hi = __uint_as_float(f2tf32(x));
    lo = x - hi;
}

__device__ __forceinline__ void mma_tf32(float* d,
                                         unsigned a0, unsigned a1, unsigned a2, unsigned a3,
                                         unsigned b0, unsigned b1) {
    asm volatile(
        "mma.sync.aligned.m16n8k8.row.col.f32.tf32.tf32.f32 "
        "{%0,%1,%2,%3}, {%4,%5,%6,%7}, {%8,%9}, {%0,%1,%2,%3};"
        : "+f"(d[0]), "+f"(d[1]), "+f"(d[2]), "+f"(d[3])
        : "r"(a0), "r"(a1), "r"(a2), "r"(a3), "r"(b0), "r"(b1));
}

__device__ __forceinline__ void mma3(float* d, const unsigned* ah, const unsigned* al,
                                     unsigned bh0, unsigned bh1, unsigned bl0, unsigned bl1) {
    mma_tf32(d, ah[0], ah[1], ah[2], ah[3], bh0, bh1);
    mma_tf32(d, ah[0], ah[1], ah[2], ah[3], bl0, bl1);
    mma_tf32(d, al[0], al[1], al[2], al[3], bh0, bh1);
}

__device__ __forceinline__ void cp_async16(unsigned dst, const void* src) {
    asm volatile("cp.async.cg.shared.global [%0], [%1], 16;" :: "r"(dst), "l"(src));
}

// ---------------- K0: fold LN affine into Wz ----------------
__global__ void prep_kernel(const float* __restrict__ Wz,
                            const float* __restrict__ lnw,
                            const float* __restrict__ lnb) {
    __shared__ float red[8];
    int c = threadIdx.x;
    float wc = lnw[c], bc = lnb[c];
    for (int h = 0; h < NH; h++) {
        float wz = Wz[h * CZ + c];
        float a = wz * wc;
        g_A[h * CZ + c] = a;
        float sa = a, cb = wz * bc;
        for (int o = 16; o; o >>= 1) {
            sa += __shfl_down_sync(0xffffffffu, sa, o);
            cb += __shfl_down_sync(0xffffffffu, cb, o);
        }
        if ((c & 31) == 0) { red[c >> 5] = sa; red[4 + (c >> 5)] = cb; }
        __syncthreads();
        if (c == 0) {
            g_SA[h] = red[0] + red[1] + red[2] + red[3];
            g_CB[h] = red[4] + red[5] + red[6] + red[7];
        }
        __syncthreads();
    }
}

// ---------------- K1: projections, dual-plane 3xTF32, BM=BN=64 (r10 proven) ----------------
__global__ void proj_kernel(const float* __restrict__ s,
                            const float* __restrict__ Wq, const float* __restrict__ bq,
                            const float* __restrict__ Wk, const float* __restrict__ Wv,
                            const float* __restrict__ Wg) {
    __shared__ float sh[64][20], sl[64][20], wh[64][20], wl[64][20];
    int w = blockIdx.z;
    const float* W = (w == 0) ? Wq : (w == 1) ? Wk : (w == 2) ? Wv : Wg;
    float* C = (w == 0) ? g_q : (w == 1) ? g_k : (w == 2) ? g_v : g_g;
    int bm = blockIdx.y * 64, bn = blockIdx.x * 64;
    int tid = threadIdx.x;
    int wid = tid >> 5, lane = tid & 31;
    int mtile = wid & 3, ntile = wid >> 2;
    int gr = lane >> 2, tig = lane & 3;
    int lr = tid >> 2, lc = (tid & 3) * 4;
    float acc[4][4] = {};

    for (int k0 = 0; k0 < D_MODEL; k0 += 16) {
        {
            float4 v = *reinterpret_cast<const float4*>(&s[(bm + lr) * D_MODEL + k0 + lc]);
            split2(v.x, sh[lr][lc], sl[lr][lc]);
            split2(v.y, sh[lr][lc + 1], sl[lr][lc + 1]);
            split2(v.z, sh[lr][lc + 2], sl[lr][lc + 2]);
            split2(v.w, sh[lr][lc + 3], sl[lr][lc + 3]);
            float4 u = *reinterpret_cast<const float4*>(&W[(bn + lr) * D_MODEL + k0 + lc]);
            split2(u.x, wh[lr][lc], wl[lr][lc]);
            split2(u.y, wh[lr][lc + 1], wl[lr][lc + 1]);
            split2(u.z, wh[lr][lc + 2], wl[lr][lc + 2]);
            split2(u.w, wh[lr][lc + 3], wl[lr][lc + 3]);
        }
        __syncthreads();
#pragma unroll
        for (int kk = 0; kk < 16; kk += 8) {
            int mr = mtile * 16 + gr;
            unsigned ah[4], al[4];
            ah[0] = bits(sh[mr][kk + tig]);     al[0] = bits(sl[mr][kk + tig]);
            ah[1] = bits(sh[mr + 8][kk + tig]); al[1] = bits(sl[mr + 8][kk + tig]);
            ah[2] = bits(sh[mr][kk + tig + 4]);     al[2] = bits(sl[mr][kk + tig + 4]);
            ah[3] = bits(sh[mr + 8][kk + tig + 4]); al[3] = bits(sl[mr + 8][kk + tig + 4]);
#pragma unroll
            for (int ni = 0; ni < 4; ni++) {
                int nr = ntile * 32 + ni * 8 + gr;
                unsigned bh0 = bits(wh[nr][kk + tig]), bl0 = bits(wl[nr][kk + tig]);
                unsigned bh1 = bits(wh[nr][kk + tig + 4]), bl1 = bits(wl[nr][kk + tig + 4]);
                mma3(acc[ni], ah, al, bh0, bh1, bl0, bl1);
            }
        }
        __syncthreads();
    }
#pragma unroll
    for (int ni = 0; ni < 4; ni++) {
        int m = bm + mtile * 16 + gr;
        int n = bn + ntile * 32 + ni * 8 + 2 * tig;
        float b0 = 0.f, b1 = 0.f;
        if (w == 0) { b0 = bq[n]; b1 = bq[n + 1]; }
        *reinterpret_cast<float2*>(&C[m * D_MODEL + n]) =
            make_float2(acc[ni][0] + b0, acc[ni][1] + b1);
        *reinterpret_cast<float2*>(&C[(m + 8) * D_MODEL + n]) =
            make_float2(acc[ni][2] + b0, acc[ni][3] + b1);
    }
}

// ---------------- K2: pair bias, double-buffered cp.async (r13 proven) ----------------
__global__ void bias_kernel(const float* __restrict__ z) {
    extern __shared__ float bsm[];
    float* zbuf[2] = {bsm, bsm + 64 * 132};
    float* As = bsm + 2 * 64 * 132;
    float* mu_s = As + 16 * 132;
    float* rs_s = mu_s + 64;
    int j0 = blockIdx.x * 64;
    int ibase = blockIdx.y * BIAS_ITILES;
    int tid = threadIdx.x;

    for (int e = tid; e < 16 * 32; e += 256) {
        int h = e >> 5, c4 = (e & 31) * 4;
        float4 v = *reinterpret_cast<const float4*>(&g_A[h * CZ + c4]);
        *reinterpret_cast<float4*>(&As[h * 132 + c4]) = v;
    }
    {
        const float* zb = z + ((size_t)ibase * N_TOK + j0) * CZ;
        unsigned dst = (unsigned)__cvta_generic_to_shared(zbuf[0]);
#pragma unroll
        for (int it = 0; it < 8; it++) {
            int f4 = tid + it * 256;
            int r = f4 >> 5, c4 = f4 & 31;
            cp_async16(dst + (r * 132 + c4 * 4) * 4, zb + r * CZ + c4 * 4);
        }
        asm volatile("cp.async.commit_group;");
    }

    int w = tid >> 5, lane = tid & 31;
    int mtile = w & 3, ntile = w >> 2;
    int gr = lane >> 2, tig = lane & 3;

    for (int t = 0; t < BIAS_ITILES; t++) {
        float* cur = zbuf[t & 1];
        if (t + 1 < BIAS_ITILES) {
            const float* zb = z + ((size_t)(ibase + t + 1) * N_TOK + j0) * CZ;
            unsigned dst = (unsigned)__cvta_generic_to_shared(zbuf[(t + 1) & 1]);
#pragma unroll
            for (int it = 0; it < 8; it++) {
                int f4 = tid + it * 256;
                int r = f4 >> 5, c4 = f4 & 31;
                cp_async16(dst + (r * 132 + c4 * 4) * 4, zb + r * CZ + c4 * 4);
            }
            asm volatile("cp.async.commit_group;");
            asm volatile("cp.async.wait_group 1;");
        } else {
            asm volatile("cp.async.wait_group 0;");
        }
        __syncthreads();

        {
            int row = tid >> 2, sub = tid & 3;
            float sm = 0.f, sq = 0.f;
#pragma unroll
            for (int c4 = 0; c4 < 8; c4++) {
                float4 v = *reinterpret_cast<float4*>(&cur[row * 132 + (sub * 8 + c4) * 4]);
                sm += v.x + v.y + v.z + v.w;
                sq += v.x * v.x + v.y * v.y + v.z * v.z + v.w * v.w;
            }
            sm += __shfl_xor_sync(0xffffffffu, sm, 1);
            sm += __shfl_xor_sync(0xffffffffu, sm, 2);
            sq += __shfl_xor_sync(0xffffffffu, sq, 1);
            sq += __shfl_xor_sync(0xffffffffu, sq, 2);
            if (sub == 0) {
                float m = sm * (1.0f / CZ);
                float var = sq * (1.0f / CZ) - m * m;
                mu_s[row] = m;
                rs_s[row] = rsqrtf(var + LN_EPS);
            }
        }
        __syncthreads();

        const float* zr0 = &cur[(mtile * 16 + gr) * 132];
        const float* zr1 = &cur[(mtile * 16 + gr + 8) * 132];
        const float* ar = &As[(ntile * 8 + gr) * 132];

        float d[4] = {};
#pragma unroll
        for (int k0 = 0; k0 < CZ; k0 += 8) {
            unsigned a0 = f2tf32(zr0[k0 + tig]);
            unsigned a1 = f2tf32(zr1[k0 + tig]);
            unsigned a2 = f2tf32(zr0[k0 + tig + 4]);
            unsigned a3 = f2tf32(zr1[k0 + tig + 4]);
            unsigned b0 = f2tf32(ar[k0 + tig]);
            unsigned b1 = f2tf32(ar[k0 + tig + 4]);
            mma_tf32(d, a0, a1, a2, a3, b0, b1);
        }

        int i = ibase + t;
        int jl = mtile * 16 + gr;
        int jh = jl + 8;
        int h0 = ntile * 8 + 2 * tig, h1 = h0 + 1;
        float mu_l = mu_s[jl], rs_l = rs_s[jl];
        float mu_h = mu_s[jh], rs_h = rs_s[jh];
        float sa0 = g_SA[h0], cb0 = g_CB[h0];
        float sa1 = g_SA[h1], cb1 = g_CB[h1];
        g_logits[((size_t)h0 * N_TOK + i) * N_TOK + j0 + jl] = rs_l * (d[0] - mu_l * sa0) + cb0;
        g_logits[((size_t)h1 * N_TOK + i) * N_TOK + j0 + jl] = rs_l * (d[1] - mu_l * sa1) + cb1;
        g_logits[((size_t)h0 * N_TOK + i) * N_TOK + j0 + jh] = rs_h * (d[2] - mu_h * sa0) + cb0;
        g_logits[((size_t)h1 * N_TOK + i) * N_TOK + j0 + jh] = rs_h * (d[3] - mu_h * sa1) + cb1;
        __syncthreads();
    }
}

// ---------------- K3: fused attention, 32 q-rows/block, 2 m-frags per warp (r13 proven) ----------------
__global__ __launch_bounds__(256, 2) void attn_kernel() {
    extern __shared__ float sm_[];
    float* Ps = sm_;                     // [32][PSW]; front 8192 reused for reduction
    float* inv_s = Ps + 32 * PSW;        // [32]
    int h = blockIdx.y;
    int i0 = blockIdx.x * 32;
    int tid = threadIdx.x;
    int wid = tid >> 5, lane = tid & 31;
    int gr = lane >> 2, tig = lane & 3;
    const float scale = 0.17677669529663687f;
    int jw = wid * 96;

    {
        unsigned qa_h[2][4][4], qa_l[2][4][4];
        const float* qb = g_q + (size_t)i0 * D_MODEL + h * DH;
#pragma unroll
        for (int mi = 0; mi < 2; mi++) {
#pragma unroll
            for (int kk4 = 0; kk4 < 4; kk4++) {
                int k = kk4 * 8;
                int r0 = mi * 16 + gr, r1 = mi * 16 + gr + 8;
                float hi, lo;
                split2(qb[r0 * D_MODEL + k + tig] * scale, hi, lo);
                qa_h[mi][kk4][0] = bits(hi); qa_l[mi][kk4][0] = bits(lo);
                split2(qb[r1 * D_MODEL + k + tig] * scale, hi, lo);
                qa_h[mi][kk4][1] = bits(hi); qa_l[mi][kk4][1] = bits(lo);
                split2(qb[r0 * D_MODEL + k + tig + 4] * scale, hi, lo);
                qa_h[mi][kk4][2] = bits(hi); qa_l[mi][kk4][2] = bits(lo);
                split2(qb[r1 * D_MODEL + k + tig + 4] * scale, hi, lo);
                qa_h[mi][kk4][3] = bits(hi); qa_l[mi][kk4][3] = bits(lo);
            }
        }

        const float* kb = g_k + h * DH;
        const float* bb = g_logits + ((size_t)h * N_TOK + i0) * N_TOK;
#pragma unroll
        for (int f = 0; f < 12; f++) {
            int n0 = jw + f * 8;
            float acc[2][4] = {};
#pragma unroll
            for (int kk4 = 0; kk4 < 4; kk4++) {
                int k = kk4 * 8;
                float hi, lo;
                unsigned bh0, bl0, bh1, bl1;
                split2(kb[(n0 + gr) * D_MODEL + k + tig], hi, lo); bh0 = bits(hi); bl0 = bits(lo);
                split2(kb[(n0 + gr) * D_MODEL + k + tig + 4], hi, lo); bh1 = bits(hi); bl1 = bits(lo);
#pragma unroll
                for (int mi = 0; mi < 2; mi++)
                    mma3(acc[mi], qa_h[mi][kk4], qa_l[mi][kk4], bh0, bh1, bl0, bl1);
            }
            int jc = n0 + 2 * tig;
#pragma unroll
            for (int mi = 0; mi < 2; mi++) {
                int r0 = mi * 16 + gr, r1 = mi * 16 + gr + 8;
                float2 b0 = *reinterpret_cast<const float2*>(&bb[r0 * N_TOK + jc]);
                float2 b1 = *reinterpret_cast<const float2*>(&bb[r1 * N_TOK + jc]);
                *reinterpret_cast<float2*>(&Ps[r0 * PSW + jc]) =
                    make_float2(acc[mi][0] + b0.x, acc[mi][1] + b0.y);
                *reinterpret_cast<float2*>(&Ps[r1 * PSW + jc]) =
                    make_float2(acc[mi][2] + b1.x, acc[mi][3] + b1.y);
            }
        }
    }
    __syncthreads();

#pragma unroll
    for (int rr = 0; rr < 4; rr++) {
        int r = wid * 4 + rr;
        float v[24];
        float mx = -1e30f;
#pragma unroll
        for (int t = 0; t < 24; t++) {
            v[t] = Ps[r * PSW + lane + 32 * t];
            mx = fmaxf(mx, v[t]);
        }
#pragma unroll
        for (int o = 16; o; o >>= 1) mx = fmaxf(mx, __shfl_xor_sync(0xffffffffu, mx, o));
        float sum = 0.f;
#pragma unroll
        for (int t = 0; t < 24; t++) { v[t] = __expf(v[t] - mx); sum += v[t]; }
#pragma unroll
        for (int o = 16; o; o >>= 1) sum += __shfl_xor_sync(0xffffffffu, sum, o);
        if (lane == 0) inv_s[r] = 1.0f / sum;
#pragma unroll
        for (int t = 0; t < 24; t++) Ps[r * PSW + lane + 32 * t] = v[t];
    }
    __syncthreads();

    float acc2[2][4][4] = {};
    {
        const float* vb = g_v + h * DH;
#pragma unroll
        for (int kk = 0; kk < 96; kk += 8) {
            int kg = jw + kk;
            unsigned ah[2][4], al[2][4];
            float hi, lo;
#pragma unroll
            for (int mi = 0; mi < 2; mi++) {
                int r0 = mi * 16 + gr, r1 = mi * 16 + gr + 8;
                split2(Ps[r0 * PSW + kg + tig], hi, lo);     ah[mi][0] = bits(hi); al[mi][0] = bits(lo);
                split2(Ps[r1 * PSW + kg + tig], hi, lo);     ah[mi][1] = bits(hi); al[mi][1] = bits(lo);
                split2(Ps[r0 * PSW + kg + tig + 4], hi, lo); ah[mi][2] = bits(hi); al[mi][2] = bits(lo);
                split2(Ps[r1 * PSW + kg + tig + 4], hi, lo); ah[mi][3] = bits(hi); al[mi][3] = bits(lo);
            }
#pragma unroll
            for (int ni = 0; ni < 4; ni++) {
                float b0f = vb[(kg + tig) * D_MODEL + ni * 8 + gr];
                float b1f = vb[(kg + tig + 4) * D_MODEL + ni * 8 + gr];
                unsigned bh0, bl0, bh1, bl1;
                split2(b0f, hi, lo); bh0 = bits(hi); bl0 = bits(lo);
                split2(b1f, hi, lo); bh1 = bits(hi); bl1 = bits(lo);
#pragma unroll
                for (int mi = 0; mi < 2; mi++)
                    mma3(acc2[mi][ni], ah[mi], al[mi], bh0, bh1, bl0, bl1);
            }
        }
    }
    __syncthreads();  // all Ps reads done; safe to reuse Ps front as reduction buffer

    float* red = Ps;
#pragma unroll
    for (int mi = 0; mi < 2; mi++) {
#pragma unroll
        for (int ni = 0; ni < 4; ni++) {
            int r0 = mi * 16 + gr, r1 = mi * 16 + gr + 8;
            *reinterpret_cast<float2*>(&red[wid * 1024 + r0 * 32 + ni * 8 + 2 * tig]) =
                make_float2(acc2[mi][ni][0], acc2[mi][ni][1]);
            *reinterpret_cast<float2*>(&red[wid * 1024 + r1 * 32 + ni * 8 + 2 * tig]) =
                make_float2(acc2[mi][ni][2], acc2[mi][ni][3]);
        }
    }
    __syncthreads();
    {
        int e0 = tid * 4;
        int i = e0 >> 5, d = e0 & 31;
        float4 sum = make_float4(0.f, 0.f, 0.f, 0.f);
#pragma unroll
        for (int w = 0; w < 8; w++) {
            float4 p = *reinterpret_cast<float4*>(&red[w * 1024 + e0]);
            sum.x += p.x; sum.y += p.y; sum.z += p.z; sum.w += p.w;
        }
        float iv = inv_s[i];
        *reinterpret_cast<float4*>(&g_o[(size_t)(i0 + i) * D_MODEL + h * DH + d]) =
            make_float4(sum.x * iv, sum.y * iv, sum.z * iv, sum.w * iv);
    }
}

// ---------------- K4: out = (o * sigmoid(g)) @ Wo^T, dual-plane, BM=BN=64 (r10 proven) ----------------
__global__ void out_kernel(const float* __restrict__ Wo, float* __restrict__ out) {
    __shared__ float sh[64][20], sl[64][20], wh[64][20], wl[64][20];
    int bm = blockIdx.y * 64, bn = blockIdx.x * 64;
    int tid = threadIdx.x;
    int wid = tid >> 5, lane = tid & 31;
    int mtile = wid & 3, ntile = wid >> 2;
    int gr = lane >> 2, tig = lane & 3;
    int lr = tid >> 2, lc = (tid & 3) * 4;
    float acc[4][4] = {};

    for (int k0 = 0; k0 < D_MODEL; k0 += 16) {
        {
            float4 va = *reinterpret_cast<const float4*>(&g_o[(bm + lr) * D_MODEL + k0 + lc]);
            float4 vg = *reinterpret_cast<const float4*>(&g_g[(bm + lr) * D_MODEL + k0 + lc]);
            va.x *= 1.0f / (1.0f + __expf(-vg.x));
            va.y *= 1.0f / (1.0f + __expf(-vg.y));
            va.z *= 1.0f / (1.0f + __expf(-vg.z));
            va.w *= 1.0f / (1.0f + __expf(-vg.w));
            split2(va.x, sh[lr][lc], sl[lr][lc]);
            split2(va.y, sh[lr][lc + 1], sl[lr][lc + 1]);
            split2(va.z, sh[lr][lc + 2], sl[lr][lc + 2]);
            split2(va.w, sh[lr][lc + 3], sl[lr][lc + 3]);
            float4 u = *reinterpret_cast<const float4*>(&Wo[(bn + lr) * D_MODEL + k0 + lc]);
            split2(u.x, wh[lr][lc], wl[lr][lc]);
            split2(u.y, wh[lr][lc + 1], wl[lr][lc + 1]);
            split2(u.z, wh[lr][lc + 2], wl[lr][lc + 2]);
            split2(u.w, wh[lr][lc + 3], wl[lr][lc + 3]);
        }
        __syncthreads();
#pragma unroll
        for (int kk = 0; kk < 16; kk += 8) {
            int mr = mtile * 16 + gr;
            unsigned ah[4], al[4];
            ah[0] = bits(sh[mr][kk + tig]);     al[0] = bits(sl[mr][kk + tig]);
            ah[1] = bits(sh[mr + 8][kk + tig]); al[1] = bits(sl[mr + 8][kk + tig]);
            ah[2] = bits(sh[mr][kk + tig + 4]);     al[2] = bits(sl[mr][kk + tig + 4]);
            ah[3] = bits(sh[mr + 8][kk + tig + 4]); al[3] = bits(sl[mr + 8][kk + tig + 4]);
#pragma unroll
            for (int ni = 0; ni < 4; ni++) {
                int nr = ntile * 32 + ni * 8 + gr;
                unsigned bh0 = bits(wh[nr][kk + tig]), bl0 = bits(wl[nr][kk + tig]);
                unsigned bh1 = bits(wh[nr][kk + tig + 4]), bl1 = bits(wl[nr][kk + tig + 4]);
                mma3(acc[ni], ah, al, bh0, bh1, bl0, bl1);
            }
        }
        __syncthreads();
    }
#pragma unroll
    for (int ni = 0; ni < 4; ni++) {
        int m = bm + mtile * 16 + gr;
        int n = bn + ntile * 32 + ni * 8 + 2 * tig;
        *reinterpret_cast<float2*>(&out[m * D_MODEL + n]) = make_float2(acc[ni][0], acc[ni][1]);
        *reinterpret_cast<float2*>(&out[(m + 8) * D_MODEL + n]) = make_float2(acc[ni][2], acc[ni][3]);
    }
}

// ---------------- launch: prep -> {proj || bias} -> attn -> out ----------------
extern "C" void kernel_launch(void* const* d_in, const int* in_sizes, int n_in,
                              void* d_out, int out_size) {
    const float* s   = (const float*)d_in[0];
    const float* z   = (const float*)d_in[1];
    const float* Wq  = (const float*)d_in[2];
    const float* bq  = (const float*)d_in[3];
    const float* Wk  = (const float*)d_in[4];
    const float* Wv  = (const float*)d_in[5];
    const float* Wg  = (const float*)d_in[6];
    const float* Wo  = (const float*)d_in[7];
    const float* lnw = (const float*)d_in[8];
    const float* lnb = (const float*)d_in[9];
    const float* Wz  = (const float*)d_in[10];
    float* out = (float*)d_out;

    const int attn_smem = (32 * PSW + 32) * 4;
    cudaFuncSetAttribute(attn_kernel, cudaFuncAttributeMaxDynamicSharedMemorySize, attn_smem);
    const int bias_smem = (2 * 64 * 132 + 16 * 132 + 128) * 4;
    cudaFuncSetAttribute(bias_kernel, cudaFuncAttributeMaxDynamicSharedMemorySize, bias_smem);

    // side stream + events for the proj || bias fork (created per call; cheap,
    // host-side only, keeps kernel_launch deterministic and capture-legal)
    cudaStream_t s2;
    cudaStreamCreateWithFlags(&s2, cudaStreamNonBlocking);
    cudaEvent_t eFork, eJoin;
    cudaEventCreateWithFlags(&eFork, cudaEventDisableTiming);
    cudaEventCreateWithFlags(&eJoin, cudaEventDisableTiming);

    prep_kernel<<<1, 128>>>(Wz, lnw, lnb);
    cudaEventRecord(eFork, 0);
    cudaStreamWaitEvent(s2, eFork, 0);

    // fork: proj on side stream, bias on main stream (bias is the longer one)
    proj_kernel<<<dim3(D_MODEL / 64, N_TOK / 64, 4), 256, 0, s2>>>(s, Wq, bq, Wk, Wv, Wg);
    bias_kernel<<<dim3(N_TOK / 64, N_TOK / BIAS_ITILES), 256, bias_smem>>>(z);

    // join
    cudaEventRecord(eJoin, s2);
    cudaStreamWaitEvent(0, eJoin, 0);

    attn_kernel<<<dim3(N_TOK / 32, NH), 256, attn_smem>>>();
    out_kernel<<<dim3(D_MODEL / 64, N_TOK / 64), 256>>>(Wo, out);
}